// round 15
// baseline (speedup 1.0000x reference)
#include <cuda_runtime.h>
#include <math.h>

#define NN 50000
#define NE 1600000
#define CAP 128

typedef unsigned long long u64;
#define FULL 0xffffffffu

// ---------------- device scratch (no allocations allowed) ----------------
__device__ int   g_cnt[NN];          // zero at load; re-zeroed by agg40lsm
__device__ int   g_bsrc[NN * CAP];   // bucketed src lists by dst
__device__ float g_bw[NN * CAP];     // edge weight per bucket slot
__device__ int   g_nnz[NN];          // nonzero-edge count per node (per layer)
__device__ float g_invn[NN];
__device__ float g_rowsum[NN];
__device__ float g_degf[NN];
__device__ float g_dinv[NN];
__device__ float g_cnode[NN];
__device__ float g_rd[NN];           // rinv * dinv (src-side combined)
__device__ float g_h[NN * 128];
__device__ float g_x1[NN * 128];
__device__ float g_x2[NN * 16];

// ---------------- helpers ----------------
__device__ __forceinline__ float warp_sum(float v) {
    #pragma unroll
    for (int o = 16; o; o >>= 1) v += __shfl_xor_sync(FULL, v, o);
    return v;
}
__device__ __forceinline__ float warp_max(float v) {
    #pragma unroll
    for (int o = 16; o; o >>= 1) v = fmaxf(v, __shfl_xor_sync(FULL, v, o));
    return v;
}
__device__ __forceinline__ void fma2(u64& d, u64 a, u64 b) {
    asm("fma.rn.f32x2 %0, %1, %2, %0;" : "+l"(d) : "l"(a), "l"(b));
}
__device__ __forceinline__ u64 pack2(float lo, float hi) {
    u64 v;
    asm("mov.b64 %0, {%1, %2};" : "=l"(v) : "f"(lo), "f"(hi));
    return v;
}
__device__ __forceinline__ float2 unpack2(u64 v) {
    float2 r;
    asm("mov.b64 {%0, %1}, %2;" : "=f"(r.x), "=f"(r.y) : "l"(v));
    return r;
}
__device__ __forceinline__ float dot44(float4 a, float4 b) {
    return a.x * b.x + a.y * b.y + a.z * b.z + a.w * b.w;
}

// ---------------- fused: bucket fill (blocks 0..6249) + invn128 (rest) ----
__global__ void k_fill_invn(const int* __restrict__ src, const int* __restrict__ dst,
                            const float* __restrict__ x) {
    if (blockIdx.x < 6250) {
        int e = blockIdx.x * 256 + threadIdx.x;
        if (e < NE) {
            int d = dst[e];
            int p = atomicAdd(&g_cnt[d], 1);
            if (p < CAP) g_bsrc[d * CAP + p] = src[e];
        }
    } else {
        int w = ((blockIdx.x - 6250) * 256 + threadIdx.x) >> 5;
        int lane = threadIdx.x & 31;
        if (w >= NN) return;
        float4 v = ((const float4*)(x + (size_t)w * 128))[lane];
        float s = warp_sum(dot44(v, v));
        if (lane == 0) g_invn[w] = (s > 0.f) ? rsqrtf(s) : 0.f;
    }
}

// -- sim: 8 lanes/edge, pipelined (R13) + register nnz counter -------------
__global__ void k_sim128(const float* __restrict__ x) {
    int node = (blockIdx.x * blockDim.x + threadIdx.x) >> 5;
    int lane = threadIdx.x & 31;
    if (node >= NN) return;
    int g = (lane >> 3) & 3;   // edge group 0..3
    int j = lane & 7;          // float4 slot within group
    const float4* xr = (const float4*)x;
    const float4* brow = xr + (size_t)node * 32 + j;
    float4 b0 = brow[0], b1 = brow[8], b2 = brow[16], b3 = brow[24];
    float invd = g_invn[node];
    int cnt = min(g_cnt[node], CAP);
    const int* bs = g_bsrc + node * CAP;
    float* bw = g_bw + node * CAP;
    int nzc = 0;
    if (cnt > 0) {
        // prologue: load quad 0
        int s_cur = bs[(g < cnt) ? g : 0];
        const float4* ar = xr + (size_t)s_cur * 32 + j;
        float4 a0 = ar[0], a1 = ar[8], a2 = ar[16], a3 = ar[24];
        for (int p = 0; p < cnt; p += 4) {
            int inx = p + 4 + g;
            int s_nxt = bs[(inx < cnt) ? inx : 0];
            const float4* an = xr + (size_t)s_nxt * 32 + j;
            float4 n0 = an[0], n1 = an[8], n2 = an[16], n3 = an[24];
            float t = dot44(a0, b0) + dot44(a1, b1) + dot44(a2, b2) + dot44(a3, b3);
            t += __shfl_xor_sync(FULL, t, 4);
            t += __shfl_xor_sync(FULL, t, 2);
            t += __shfl_xor_sync(FULL, t, 1);
            int icur = p + g;
            if (j == 0 && icur < cnt) {
                float sim = t * g_invn[s_cur] * invd;
                float wv = (sim >= 0.5f && s_cur != node) ? sim : 0.f;
                bw[icur] = wv;
                if (wv != 0.f) {
                    nzc++;
                    atomicAdd(&g_rowsum[s_cur], wv);
                    atomicAdd(&g_degf[s_cur], 1.f);
                }
            }
            a0 = n0; a1 = n1; a2 = n2; a3 = n3;
            s_cur = s_nxt;
        }
    }
    float nz = warp_sum((float)nzc);
    if (lane == 0) g_nnz[node] = (int)nz;
}

// 16-dim sim: warp per node, lane per bucket slot + nnz counter
__global__ void k_sim16(const float* __restrict__ x) {
    int node = (blockIdx.x * blockDim.x + threadIdx.x) >> 5;
    int lane = threadIdx.x & 31;
    if (node >= NN) return;
    const float4* pb = (const float4*)(x + (size_t)node * 16);
    float4 b0 = pb[0], b1 = pb[1], b2 = pb[2], b3 = pb[3];
    float invd = g_invn[node];
    int cnt = min(g_cnt[node], CAP);
    const int* bs = g_bsrc + node * CAP;
    float* bw = g_bw + node * CAP;
    int nzc = 0;
    for (int p = lane; p < cnt; p += 32) {
        int s = bs[p];
        const float4* pa = (const float4*)(x + (size_t)s * 16);
        float t = dot44(pa[0], b0) + dot44(pa[1], b1) + dot44(pa[2], b2) + dot44(pa[3], b3);
        float sim = t * g_invn[s] * invd;
        float wv = (sim >= 0.5f && s != node) ? sim : 0.f;
        bw[p] = wv;
        if (wv != 0.f) {
            nzc++;
            atomicAdd(&g_rowsum[s], wv);
            atomicAdd(&g_degf[s], 1.f);
        }
    }
    float nz = warp_sum((float)nzc);
    if (lane == 0) g_nnz[node] = (int)nz;
}

// ---------------- gcn degree + dinv/cnode/rd (warp per node) --------------
__global__ void k_degC() {
    int node = (blockIdx.x * blockDim.x + threadIdx.x) >> 5;
    int lane = threadIdx.x & 31;
    if (node >= NN) return;
    float acc = 0.f;
    if (g_nnz[node] != 0) {
        int cnt = min(g_cnt[node], CAP);
        const int* bs = g_bsrc + node * CAP;
        const float* bw = g_bw + node * CAP;
        for (int p = lane; p < cnt; p += 32) {
            float wv = bw[p];
            if (wv != 0.f) acc += wv * (1.f / g_rowsum[bs[p]]);  // rowsum>=wv>0
        }
        acc = warp_sum(acc);
    }
    if (lane == 0) {
        float sw = 1.f / (g_degf[node] + 1.f);
        float dv = rsqrtf(acc + sw);   // sw > 0 always
        g_dinv[node] = dv;
        g_cnode[node] = sw * dv * dv;
        float rs = g_rowsum[node];
        float rinv = (rs == 0.f) ? 1.f : 1.f / rs;
        g_rd[node] = rinv * dv;
    }
}

// ---------------- GEMM (K=128) with packed f32x2 FMA ----------------------
template <int N>
__global__ void __launch_bounds__(256) k_gemm2(const float* __restrict__ A,
                                               const float* __restrict__ W,
                                               float* __restrict__ C) {
    constexpr int CG = N / 4;
    constexpr int BR = (N == 128) ? 32 : 64;
    constexpr int RT = BR * CG / 256;
    extern __shared__ u64 Ws2[];
    for (int i = threadIdx.x; i < 64 * N; i += 256) {
        int kp = i / N, c = i % N;
        Ws2[i] = pack2(W[(2 * kp) * N + c], W[(2 * kp + 1) * N + c]);
    }
    __syncthreads();
    int cg = threadIdx.x % CG;
    int r0 = blockIdx.x * BR + (threadIdx.x / CG) * RT;
    const float4* A4 = (const float4*)A;
    u64 acc[RT][4];
    int rr[RT];
    #pragma unroll
    for (int i = 0; i < RT; i++) {
        acc[i][0] = acc[i][1] = acc[i][2] = acc[i][3] = 0ull;
        rr[i] = min(r0 + i, NN - 1);
    }
    for (int kq = 0; kq < 32; kq++) {
        const u64* w0 = Ws2 + (2 * kq) * N + cg * 4;
        const u64* w1 = w0 + N;
        u64 wa0 = w0[0], wa1 = w0[1], wa2 = w0[2], wa3 = w0[3];
        u64 wb0 = w1[0], wb1 = w1[1], wb2 = w1[2], wb3 = w1[3];
        #pragma unroll
        for (int i = 0; i < RT; i++) {
            float4 a = A4[(size_t)rr[i] * 32 + kq];
            u64 a01 = pack2(a.x, a.y);
            u64 a23 = pack2(a.z, a.w);
            fma2(acc[i][0], a01, wa0); fma2(acc[i][0], a23, wb0);
            fma2(acc[i][1], a01, wa1); fma2(acc[i][1], a23, wb1);
            fma2(acc[i][2], a01, wa2); fma2(acc[i][2], a23, wb2);
            fma2(acc[i][3], a01, wa3); fma2(acc[i][3], a23, wb3);
        }
    }
    #pragma unroll
    for (int i = 0; i < RT; i++) {
        int gr = r0 + i;
        if (gr < NN) {
            float2 c0 = unpack2(acc[i][0]), c1 = unpack2(acc[i][1]);
            float2 c2 = unpack2(acc[i][2]), c3 = unpack2(acc[i][3]);
            *(float4*)(C + (size_t)gr * N + cg * 4) =
                make_float4(c0.x + c0.y, c1.x + c1.y, c2.x + c2.y, c3.x + c3.y);
        }
    }
}

__global__ void k_gemm_k16n40(const float* __restrict__ A, const float* __restrict__ W,
                              float* __restrict__ C) {
    __shared__ float Ws[16 * 40];
    for (int i = threadIdx.x; i < 640; i += blockDim.x) Ws[i] = W[i];
    __syncthreads();
    int r = blockIdx.x * blockDim.x + threadIdx.x;
    if (r >= NN) return;
    float a[16];
    const float4* p = (const float4*)(A + (size_t)r * 16);
    #pragma unroll
    for (int j = 0; j < 4; j++) {
        float4 v = p[j];
        a[j * 4 + 0] = v.x; a[j * 4 + 1] = v.y; a[j * 4 + 2] = v.z; a[j * 4 + 3] = v.w;
    }
    float acc[40];
    #pragma unroll
    for (int c = 0; c < 40; c++) acc[c] = 0.f;
    #pragma unroll
    for (int k = 0; k < 16; k++) {
        float av = a[k];
        #pragma unroll
        for (int c = 0; c < 40; c++) acc[c] += av * Ws[k * 40 + c];
    }
    float* out = C + (size_t)r * 40;
    #pragma unroll
    for (int c = 0; c < 40; c += 4)
        *(float4*)(out + c) = make_float4(acc[c], acc[c + 1], acc[c + 2], acc[c + 3]);
}

// ---------------- aggregation (ballot scan, skipped when nnz==0) ----------
__global__ void k_agg128(const float* __restrict__ h, const float* __restrict__ b,
                         float* __restrict__ out) {
    int node = (blockIdx.x * blockDim.x + threadIdx.x) >> 5;
    int lane = threadIdx.x & 31;
    if (node >= NN) return;
    float dv = g_dinv[node];
    float c0 = g_cnode[node];
    const float4* hr = (const float4*)h;
    float4 hv = hr[(size_t)node * 32 + lane];
    float4 bv = ((const float4*)b)[lane];
    float4 acc = make_float4(c0 * hv.x + bv.x, c0 * hv.y + bv.y,
                             c0 * hv.z + bv.z, c0 * hv.w + bv.w);
    if (g_nnz[node] != 0) {
        int cnt = min(g_cnt[node], CAP);
        const int* bs = g_bsrc + node * CAP;
        const float* bw = g_bw + node * CAP;
        for (int base = 0; base < cnt; base += 32) {
            int i = base + lane;
            float wv = (i < cnt) ? bw[i] : 0.f;
            int sl = (i < cnt) ? bs[i] : 0;
            float cl = (wv != 0.f) ? wv * g_rd[sl] * dv : 0.f;
            unsigned m = __ballot_sync(FULL, wv != 0.f);
            while (m) {
                int bit = __ffs(m) - 1;
                m &= m - 1;
                float c = __shfl_sync(FULL, cl, bit);
                int s = __shfl_sync(FULL, sl, bit);
                float4 xv = hr[(size_t)s * 32 + lane];
                acc.x += c * xv.x; acc.y += c * xv.y; acc.z += c * xv.z; acc.w += c * xv.w;
            }
        }
    }
    acc.x = fmaxf(acc.x, 0.f); acc.y = fmaxf(acc.y, 0.f);
    acc.z = fmaxf(acc.z, 0.f); acc.w = fmaxf(acc.w, 0.f);
    ((float4*)(out + (size_t)node * 128))[lane] = acc;
    float s2 = warp_sum(dot44(acc, acc));
    if (lane == 0) {
        g_invn[node] = (s2 > 0.f) ? rsqrtf(s2) : 0.f;
        g_rowsum[node] = 0.f;
        g_degf[node] = 0.f;
    }
}

__global__ void k_agg16(const float* __restrict__ h, const float* __restrict__ b,
                        float* __restrict__ out) {
    int node = (blockIdx.x * blockDim.x + threadIdx.x) >> 5;
    int lane = threadIdx.x & 31;
    if (node >= NN) return;
    int j = lane & 15;
    float dv = g_dinv[node];
    float c0 = g_cnode[node];
    float acc = 0.f;
    if (g_nnz[node] != 0) {
        int cnt = min(g_cnt[node], CAP);
        const int* bs = g_bsrc + node * CAP;
        const float* bw = g_bw + node * CAP;
        for (int base = 0; base < cnt; base += 32) {
            int i = base + lane;
            float wv = (i < cnt) ? bw[i] : 0.f;
            int sl = (i < cnt) ? bs[i] : 0;
            float cl = (wv != 0.f) ? wv * g_rd[sl] * dv : 0.f;
            unsigned m = __ballot_sync(FULL, wv != 0.f);
            while (m) {
                int bit = __ffs(m) - 1;
                m &= m - 1;
                float c = __shfl_sync(FULL, cl, bit);
                int s = __shfl_sync(FULL, sl, bit);
                acc += c * h[(size_t)s * 16 + j];
            }
        }
    }
    float r = fmaxf(acc + c0 * h[(size_t)node * 16 + j] + b[j], 0.f);
    if (lane < 16) out[(size_t)node * 16 + j] = r;
    float s2 = warp_sum((lane < 16) ? r * r : 0.f);
    if (lane == 0) {
        g_invn[node] = (s2 > 0.f) ? rsqrtf(s2) : 0.f;
        g_rowsum[node] = 0.f;
        g_degf[node] = 0.f;
    }
}

__global__ void k_agg40lsm(const float* __restrict__ h, const float* __restrict__ b,
                           float* __restrict__ out) {
    int node = (blockIdx.x * blockDim.x + threadIdx.x) >> 5;
    int lane = threadIdx.x & 31;
    if (node >= NN) return;
    float dv = g_dinv[node];
    float c0 = g_cnode[node];
    const float* hn = h + (size_t)node * 40;
    float a0 = c0 * hn[lane] + b[lane];
    float a1 = (lane < 8) ? c0 * hn[32 + lane] + b[32 + lane] : 0.f;
    if (g_nnz[node] != 0) {
        int cnt = min(g_cnt[node], CAP);
        const int* bs = g_bsrc + node * CAP;
        const float* bw = g_bw + node * CAP;
        for (int base = 0; base < cnt; base += 32) {
            int i = base + lane;
            float wv = (i < cnt) ? bw[i] : 0.f;
            int sl = (i < cnt) ? bs[i] : 0;
            float cl = (wv != 0.f) ? wv * g_rd[sl] * dv : 0.f;
            unsigned m = __ballot_sync(FULL, wv != 0.f);
            while (m) {
                int bit = __ffs(m) - 1;
                m &= m - 1;
                float c = __shfl_sync(FULL, cl, bit);
                int s = __shfl_sync(FULL, sl, bit);
                const float* hs = h + (size_t)s * 40;
                a0 += c * hs[lane];
                if (lane < 8) a1 += c * hs[32 + lane];
            }
        }
    }
    float m = warp_max((lane < 8) ? fmaxf(a0, a1) : a0);
    float se = warp_sum(expf(a0 - m) + ((lane < 8) ? expf(a1 - m) : 0.f));
    float l = logf(se) + m;
    float* on = out + (size_t)node * 40;
    on[lane] = a0 - l;
    if (lane < 8) on[32 + lane] = a1 - l;
    if (lane == 0) {            // leave all per-call accumulators zeroed
        g_rowsum[node] = 0.f;
        g_degf[node] = 0.f;
        g_cnt[node] = 0;
    }
}

// ---------------- launch ----------------
extern "C" void kernel_launch(void* const* d_in, const int* in_sizes, int n_in,
                              void* d_out, int out_size) {
    const float* x0 = (const float*)d_in[0];
    const int* ei = (const int*)d_in[1];
    const float* W1 = (const float*)d_in[2];
    const float* b1 = (const float*)d_in[3];
    const float* W2 = (const float*)d_in[4];
    const float* b2 = (const float*)d_in[5];
    const float* W3 = (const float*)d_in[6];
    const float* b3 = (const float*)d_in[7];
    const int* src = ei;
    const int* dst = ei + NE;
    float* out = (float*)d_out;

    // one-time host-side resources (no device memory involved)
    static cudaStream_t s2 = nullptr;
    static cudaEvent_t evF, evG1, evG2, evG3, evA1, evA2;
    if (!s2) {
        cudaStreamCreateWithFlags(&s2, cudaStreamNonBlocking);
        cudaEventCreateWithFlags(&evF, cudaEventDisableTiming);
        cudaEventCreateWithFlags(&evG1, cudaEventDisableTiming);
        cudaEventCreateWithFlags(&evG2, cudaEventDisableTiming);
        cudaEventCreateWithFlags(&evG3, cudaEventDisableTiming);
        cudaEventCreateWithFlags(&evA1, cudaEventDisableTiming);
        cudaEventCreateWithFlags(&evA2, cudaEventDisableTiming);
        cudaFuncSetAttribute(k_gemm2<128>, cudaFuncAttributeMaxDynamicSharedMemorySize,
                             64 * 128 * 8);
        cudaFuncSetAttribute(k_gemm2<16>, cudaFuncAttributeMaxDynamicSharedMemorySize,
                             64 * 16 * 8);
    }

    void *ph, *px1, *px2;
    cudaGetSymbolAddress(&ph, g_h);
    cudaGetSymbolAddress(&px1, g_x1);
    cudaGetSymbolAddress(&px2, g_x2);
    float* h = (float*)ph;
    float* x1 = (float*)px1;
    float* x2 = (float*)px2;

    const int TB = 256;
    const int nbN = (NN + TB - 1) / TB;        // 196
    const int nbNw = (NN * 32 + TB - 1) / TB;  // 6250 (warp per node)

    // fork side stream
    cudaEventRecord(evF, 0);
    cudaStreamWaitEvent(s2, evF, 0);

    // s2: GEMM1 (only depends on x0, W1)
    k_gemm2<128><<<(NN + 31) / 32, 256, 64 * 128 * 8, s2>>>(x0, W1, h);
    cudaEventRecord(evG1, s2);

    // main: CSR build + norms + attention chain for layer 1
    k_fill_invn<<<6250 + nbNw, TB>>>(src, dst, x0);
    k_sim128<<<nbNw, TB>>>(x0);
    k_degC<<<nbNw, TB>>>();
    cudaStreamWaitEvent(0, evG1, 0);
    k_agg128<<<nbNw, TB>>>(h, b1, x1);    // + relu + invn(x1) + re-zero
    cudaEventRecord(evA1, 0);

    // s2: GEMM2 after agg128 produced x1 (g_h free again after agg128)
    cudaStreamWaitEvent(s2, evA1, 0);
    k_gemm2<16><<<(NN + 63) / 64, 256, 64 * 16 * 8, s2>>>(x1, W2, h);
    cudaEventRecord(evG2, s2);

    // main: layer-2 attention chain (overlaps gemm2)
    k_sim128<<<nbNw, TB>>>(x1);
    k_degC<<<nbNw, TB>>>();
    cudaStreamWaitEvent(0, evG2, 0);
    k_agg16<<<nbNw, TB>>>(h, b2, x2);     // + relu + invn(x2) + re-zero
    cudaEventRecord(evA2, 0);

    // s2: GEMM3 after agg16 produced x2
    cudaStreamWaitEvent(s2, evA2, 0);
    k_gemm_k16n40<<<nbN, TB, 0, s2>>>(x2, W3, h);
    cudaEventRecord(evG3, s2);

    // main: layer-3 attention chain (overlaps gemm3)
    k_sim16<<<nbNw, TB>>>(x2);
    k_degC<<<nbNw, TB>>>();
    cudaStreamWaitEvent(0, evG3, 0);
    k_agg40lsm<<<nbNw, TB>>>(h, b3, out);  // + re-zero rowsum/degf/cnt
}

// round 16
// speedup vs baseline: 1.1155x; 1.1155x over previous
#include <cuda_runtime.h>
#include <math.h>

#define NN 50000
#define NE 1600000
#define CAP 128

typedef unsigned long long u64;
#define FULL 0xffffffffu

// ---------------- device scratch (no allocations allowed) ----------------
__device__ int   g_cnt[NN];          // zero at load; re-zeroed by agg40lsm
__device__ int   g_bsrc[NN * CAP];   // bucketed src lists by dst
__device__ float g_bw[NN * CAP];     // edge weight per bucket slot
__device__ float g_invn[NN];
__device__ float g_rowsum[NN];
__device__ float g_degf[NN];
__device__ float g_dinv[NN];
__device__ float g_cnode[NN];
__device__ float g_rd[NN];           // rinv * dinv (src-side combined)
__device__ float g_h[NN * 128];
__device__ float g_x1[NN * 128];
__device__ float g_x2[NN * 16];

// ---------------- helpers ----------------
__device__ __forceinline__ float warp_sum(float v) {
    #pragma unroll
    for (int o = 16; o; o >>= 1) v += __shfl_xor_sync(FULL, v, o);
    return v;
}
__device__ __forceinline__ float warp_max(float v) {
    #pragma unroll
    for (int o = 16; o; o >>= 1) v = fmaxf(v, __shfl_xor_sync(FULL, v, o));
    return v;
}
__device__ __forceinline__ void fma2(u64& d, u64 a, u64 b) {
    asm("fma.rn.f32x2 %0, %1, %2, %0;" : "+l"(d) : "l"(a), "l"(b));
}
__device__ __forceinline__ u64 pack2(float lo, float hi) {
    u64 v;
    asm("mov.b64 %0, {%1, %2};" : "=l"(v) : "f"(lo), "f"(hi));
    return v;
}
__device__ __forceinline__ float2 unpack2(u64 v) {
    float2 r;
    asm("mov.b64 {%0, %1}, %2;" : "=f"(r.x), "=f"(r.y) : "l"(v));
    return r;
}
__device__ __forceinline__ float dot44(float4 a, float4 b) {
    return a.x * b.x + a.y * b.y + a.z * b.z + a.w * b.w;
}

// ---------------- fused: bucket fill (blocks 0..6249) + invn128 (rest) ----
__global__ void k_fill_invn(const int* __restrict__ src, const int* __restrict__ dst,
                            const float* __restrict__ x) {
    if (blockIdx.x < 6250) {
        int e = blockIdx.x * 256 + threadIdx.x;
        if (e < NE) {
            int d = dst[e];
            int p = atomicAdd(&g_cnt[d], 1);
            if (p < CAP) g_bsrc[d * CAP + p] = src[e];
        }
    } else {
        int w = ((blockIdx.x - 6250) * 256 + threadIdx.x) >> 5;
        int lane = threadIdx.x & 31;
        if (w >= NN) return;
        float4 v = ((const float4*)(x + (size_t)w * 128))[lane];
        float s = warp_sum(dot44(v, v));
        if (lane == 0) g_invn[w] = (s > 0.f) ? rsqrtf(s) : 0.f;
    }
}

// -- sim: 8 lanes/edge, 4 edges/iter, software-pipelined (R13 exact) -------
__global__ void k_sim128(const float* __restrict__ x) {
    int node = (blockIdx.x * blockDim.x + threadIdx.x) >> 5;
    int lane = threadIdx.x & 31;
    if (node >= NN) return;
    int g = (lane >> 3) & 3;   // edge group 0..3
    int j = lane & 7;          // float4 slot within group
    const float4* xr = (const float4*)x;
    const float4* brow = xr + (size_t)node * 32 + j;
    float4 b0 = brow[0], b1 = brow[8], b2 = brow[16], b3 = brow[24];
    float invd = g_invn[node];
    int cnt = min(g_cnt[node], CAP);
    if (cnt <= 0) return;
    const int* bs = g_bsrc + node * CAP;
    float* bw = g_bw + node * CAP;
    // prologue: load quad 0
    int s_cur = bs[(g < cnt) ? g : 0];
    const float4* ar = xr + (size_t)s_cur * 32 + j;
    float4 a0 = ar[0], a1 = ar[8], a2 = ar[16], a3 = ar[24];
    for (int p = 0; p < cnt; p += 4) {
        // prefetch next quad (index 0 is always valid; rows clamp to bs[0])
        int inx = p + 4 + g;
        int s_nxt = bs[(inx < cnt) ? inx : 0];
        const float4* an = xr + (size_t)s_nxt * 32 + j;
        float4 n0 = an[0], n1 = an[8], n2 = an[16], n3 = an[24];
        // reduce current quad
        float t = dot44(a0, b0) + dot44(a1, b1) + dot44(a2, b2) + dot44(a3, b3);
        t += __shfl_xor_sync(FULL, t, 4);
        t += __shfl_xor_sync(FULL, t, 2);
        t += __shfl_xor_sync(FULL, t, 1);
        int icur = p + g;
        if (j == 0 && icur < cnt) {
            float sim = t * g_invn[s_cur] * invd;
            float wv = (sim >= 0.5f && s_cur != node) ? sim : 0.f;
            bw[icur] = wv;
            if (wv != 0.f) {
                atomicAdd(&g_rowsum[s_cur], wv);
                atomicAdd(&g_degf[s_cur], 1.f);
            }
        }
        a0 = n0; a1 = n1; a2 = n2; a3 = n3;
        s_cur = s_nxt;
    }
}

// 16-dim sim: warp per node, lane per bucket slot
__global__ void k_sim16(const float* __restrict__ x) {
    int node = (blockIdx.x * blockDim.x + threadIdx.x) >> 5;
    int lane = threadIdx.x & 31;
    if (node >= NN) return;
    const float4* pb = (const float4*)(x + (size_t)node * 16);
    float4 b0 = pb[0], b1 = pb[1], b2 = pb[2], b3 = pb[3];
    float invd = g_invn[node];
    int cnt = min(g_cnt[node], CAP);
    const int* bs = g_bsrc + node * CAP;
    float* bw = g_bw + node * CAP;
    for (int p = lane; p < cnt; p += 32) {
        int s = bs[p];
        const float4* pa = (const float4*)(x + (size_t)s * 16);
        float t = dot44(pa[0], b0) + dot44(pa[1], b1) + dot44(pa[2], b2) + dot44(pa[3], b3);
        float sim = t * g_invn[s] * invd;
        float wv = (sim >= 0.5f && s != node) ? sim : 0.f;
        bw[p] = wv;
        if (wv != 0.f) {
            atomicAdd(&g_rowsum[s], wv);
            atomicAdd(&g_degf[s], 1.f);
        }
    }
}

// ------- gcn degree + dinv/cnode/rd: 2 nodes per warp (16 lanes each) -----
__global__ void k_degC() {
    int idx = blockIdx.x * blockDim.x + threadIdx.x;
    int node = idx >> 4;               // 16 threads per node
    int hl = threadIdx.x & 15;         // lane within half
    if (node >= NN) return;
    int cnt = min(g_cnt[node], CAP);
    const int* bs = g_bsrc + node * CAP;
    const float* bw = g_bw + node * CAP;
    float acc = 0.f;
    for (int p = hl; p < cnt; p += 16) {
        float wv = bw[p];
        if (wv != 0.f) acc += wv * (1.f / g_rowsum[bs[p]]);  // rowsum>=wv>0
    }
    #pragma unroll
    for (int o = 8; o; o >>= 1) acc += __shfl_xor_sync(FULL, acc, o);
    if (hl == 0) {
        float sw = 1.f / (g_degf[node] + 1.f);
        float dv = rsqrtf(acc + sw);   // sw > 0 always
        g_dinv[node] = dv;
        g_cnode[node] = sw * dv * dv;
        float rs = g_rowsum[node];
        float rinv = (rs == 0.f) ? 1.f : 1.f / rs;
        g_rd[node] = rinv * dv;
    }
}

// ---------------- GEMM (K=128) with packed f32x2 FMA ----------------------
template <int N>
__global__ void __launch_bounds__(256) k_gemm2(const float* __restrict__ A,
                                               const float* __restrict__ W,
                                               float* __restrict__ C) {
    constexpr int CG = N / 4;
    constexpr int BR = (N == 128) ? 32 : 64;
    constexpr int RT = BR * CG / 256;
    extern __shared__ u64 Ws2[];
    for (int i = threadIdx.x; i < 64 * N; i += 256) {
        int kp = i / N, c = i % N;
        Ws2[i] = pack2(W[(2 * kp) * N + c], W[(2 * kp + 1) * N + c]);
    }
    __syncthreads();
    int cg = threadIdx.x % CG;
    int r0 = blockIdx.x * BR + (threadIdx.x / CG) * RT;
    const float4* A4 = (const float4*)A;
    u64 acc[RT][4];
    int rr[RT];
    #pragma unroll
    for (int i = 0; i < RT; i++) {
        acc[i][0] = acc[i][1] = acc[i][2] = acc[i][3] = 0ull;
        rr[i] = min(r0 + i, NN - 1);
    }
    for (int kq = 0; kq < 32; kq++) {
        const u64* w0 = Ws2 + (2 * kq) * N + cg * 4;
        const u64* w1 = w0 + N;
        u64 wa0 = w0[0], wa1 = w0[1], wa2 = w0[2], wa3 = w0[3];
        u64 wb0 = w1[0], wb1 = w1[1], wb2 = w1[2], wb3 = w1[3];
        #pragma unroll
        for (int i = 0; i < RT; i++) {
            float4 a = A4[(size_t)rr[i] * 32 + kq];
            u64 a01 = pack2(a.x, a.y);
            u64 a23 = pack2(a.z, a.w);
            fma2(acc[i][0], a01, wa0); fma2(acc[i][0], a23, wb0);
            fma2(acc[i][1], a01, wa1); fma2(acc[i][1], a23, wb1);
            fma2(acc[i][2], a01, wa2); fma2(acc[i][2], a23, wb2);
            fma2(acc[i][3], a01, wa3); fma2(acc[i][3], a23, wb3);
        }
    }
    #pragma unroll
    for (int i = 0; i < RT; i++) {
        int gr = r0 + i;
        if (gr < NN) {
            float2 c0 = unpack2(acc[i][0]), c1 = unpack2(acc[i][1]);
            float2 c2 = unpack2(acc[i][2]), c3 = unpack2(acc[i][3]);
            *(float4*)(C + (size_t)gr * N + cg * 4) =
                make_float4(c0.x + c0.y, c1.x + c1.y, c2.x + c2.y, c3.x + c3.y);
        }
    }
}

__global__ void k_gemm_k16n40(const float* __restrict__ A, const float* __restrict__ W,
                              float* __restrict__ C) {
    __shared__ float Ws[16 * 40];
    for (int i = threadIdx.x; i < 640; i += blockDim.x) Ws[i] = W[i];
    __syncthreads();
    int r = blockIdx.x * blockDim.x + threadIdx.x;
    if (r >= NN) return;
    float a[16];
    const float4* p = (const float4*)(A + (size_t)r * 16);
    #pragma unroll
    for (int j = 0; j < 4; j++) {
        float4 v = p[j];
        a[j * 4 + 0] = v.x; a[j * 4 + 1] = v.y; a[j * 4 + 2] = v.z; a[j * 4 + 3] = v.w;
    }
    float acc[40];
    #pragma unroll
    for (int c = 0; c < 40; c++) acc[c] = 0.f;
    #pragma unroll
    for (int k = 0; k < 16; k++) {
        float av = a[k];
        #pragma unroll
        for (int c = 0; c < 40; c++) acc[c] += av * Ws[k * 40 + c];
    }
    float* out = C + (size_t)r * 40;
    #pragma unroll
    for (int c = 0; c < 40; c += 4)
        *(float4*)(out + c) = make_float4(acc[c], acc[c + 1], acc[c + 2], acc[c + 3]);
}

// ---------------- aggregation (ballot-compacted edge loop, R13) -----------
__global__ void k_agg128(const float* __restrict__ h, const float* __restrict__ b,
                         float* __restrict__ out) {
    int node = (blockIdx.x * blockDim.x + threadIdx.x) >> 5;
    int lane = threadIdx.x & 31;
    if (node >= NN) return;
    float dv = g_dinv[node];
    float c0 = g_cnode[node];
    const float4* hr = (const float4*)h;
    int cnt = min(g_cnt[node], CAP);
    const int* bs = g_bsrc + node * CAP;
    const float* bw = g_bw + node * CAP;
    float4 hv = hr[(size_t)node * 32 + lane];
    float4 bv = ((const float4*)b)[lane];
    float4 acc = make_float4(c0 * hv.x + bv.x, c0 * hv.y + bv.y,
                             c0 * hv.z + bv.z, c0 * hv.w + bv.w);
    for (int base = 0; base < cnt; base += 32) {
        int i = base + lane;
        float wv = (i < cnt) ? bw[i] : 0.f;
        int sl = (i < cnt) ? bs[i] : 0;
        float cl = (wv != 0.f) ? wv * g_rd[sl] * dv : 0.f;
        unsigned m = __ballot_sync(FULL, wv != 0.f);
        while (m) {
            int bit = __ffs(m) - 1;
            m &= m - 1;
            float c = __shfl_sync(FULL, cl, bit);
            int s = __shfl_sync(FULL, sl, bit);
            float4 xv = hr[(size_t)s * 32 + lane];
            acc.x += c * xv.x; acc.y += c * xv.y; acc.z += c * xv.z; acc.w += c * xv.w;
        }
    }
    acc.x = fmaxf(acc.x, 0.f); acc.y = fmaxf(acc.y, 0.f);
    acc.z = fmaxf(acc.z, 0.f); acc.w = fmaxf(acc.w, 0.f);
    ((float4*)(out + (size_t)node * 128))[lane] = acc;
    float s2 = warp_sum(dot44(acc, acc));
    if (lane == 0) {
        g_invn[node] = (s2 > 0.f) ? rsqrtf(s2) : 0.f;
        g_rowsum[node] = 0.f;
        g_degf[node] = 0.f;
    }
}

__global__ void k_agg16(const float* __restrict__ h, const float* __restrict__ b,
                        float* __restrict__ out) {
    int node = (blockIdx.x * blockDim.x + threadIdx.x) >> 5;
    int lane = threadIdx.x & 31;
    if (node >= NN) return;
    int j = lane & 15;
    float dv = g_dinv[node];
    float c0 = g_cnode[node];
    int cnt = min(g_cnt[node], CAP);
    const int* bs = g_bsrc + node * CAP;
    const float* bw = g_bw + node * CAP;
    float acc = 0.f;
    for (int base = 0; base < cnt; base += 32) {
        int i = base + lane;
        float wv = (i < cnt) ? bw[i] : 0.f;
        int sl = (i < cnt) ? bs[i] : 0;
        float cl = (wv != 0.f) ? wv * g_rd[sl] * dv : 0.f;
        unsigned m = __ballot_sync(FULL, wv != 0.f);
        while (m) {
            int bit = __ffs(m) - 1;
            m &= m - 1;
            float c = __shfl_sync(FULL, cl, bit);
            int s = __shfl_sync(FULL, sl, bit);
            acc += c * h[(size_t)s * 16 + j];
        }
    }
    float r = fmaxf(acc + c0 * h[(size_t)node * 16 + j] + b[j], 0.f);
    if (lane < 16) out[(size_t)node * 16 + j] = r;
    float s2 = warp_sum((lane < 16) ? r * r : 0.f);
    if (lane == 0) {
        g_invn[node] = (s2 > 0.f) ? rsqrtf(s2) : 0.f;
        g_rowsum[node] = 0.f;
        g_degf[node] = 0.f;
    }
}

__global__ void k_agg40lsm(const float* __restrict__ h, const float* __restrict__ b,
                           float* __restrict__ out) {
    int node = (blockIdx.x * blockDim.x + threadIdx.x) >> 5;
    int lane = threadIdx.x & 31;
    if (node >= NN) return;
    float dv = g_dinv[node];
    float c0 = g_cnode[node];
    const float* hn = h + (size_t)node * 40;
    float a0 = c0 * hn[lane] + b[lane];
    float a1 = (lane < 8) ? c0 * hn[32 + lane] + b[32 + lane] : 0.f;
    int cnt = min(g_cnt[node], CAP);
    const int* bs = g_bsrc + node * CAP;
    const float* bw = g_bw + node * CAP;
    for (int base = 0; base < cnt; base += 32) {
        int i = base + lane;
        float wv = (i < cnt) ? bw[i] : 0.f;
        int sl = (i < cnt) ? bs[i] : 0;
        float cl = (wv != 0.f) ? wv * g_rd[sl] * dv : 0.f;
        unsigned m = __ballot_sync(FULL, wv != 0.f);
        while (m) {
            int bit = __ffs(m) - 1;
            m &= m - 1;
            float c = __shfl_sync(FULL, cl, bit);
            int s = __shfl_sync(FULL, sl, bit);
            const float* hs = h + (size_t)s * 40;
            a0 += c * hs[lane];
            if (lane < 8) a1 += c * hs[32 + lane];
        }
    }
    float m = warp_max((lane < 8) ? fmaxf(a0, a1) : a0);
    float se = warp_sum(expf(a0 - m) + ((lane < 8) ? expf(a1 - m) : 0.f));
    float l = logf(se) + m;
    float* on = out + (size_t)node * 40;
    on[lane] = a0 - l;
    if (lane < 8) on[32 + lane] = a1 - l;
    if (lane == 0) {            // leave all per-call accumulators zeroed
        g_rowsum[node] = 0.f;
        g_degf[node] = 0.f;
        g_cnt[node] = 0;
    }
}

// ---------------- launch ----------------
extern "C" void kernel_launch(void* const* d_in, const int* in_sizes, int n_in,
                              void* d_out, int out_size) {
    const float* x0 = (const float*)d_in[0];
    const int* ei = (const int*)d_in[1];
    const float* W1 = (const float*)d_in[2];
    const float* b1 = (const float*)d_in[3];
    const float* W2 = (const float*)d_in[4];
    const float* b2 = (const float*)d_in[5];
    const float* W3 = (const float*)d_in[6];
    const float* b3 = (const float*)d_in[7];
    const int* src = ei;
    const int* dst = ei + NE;
    float* out = (float*)d_out;

    // one-time host-side resources (no device memory involved)
    static cudaStream_t s2 = nullptr;
    static cudaEvent_t evF, evG1, evG2, evG3, evA1, evA2;
    if (!s2) {
        cudaStreamCreateWithFlags(&s2, cudaStreamNonBlocking);
        cudaEventCreateWithFlags(&evF, cudaEventDisableTiming);
        cudaEventCreateWithFlags(&evG1, cudaEventDisableTiming);
        cudaEventCreateWithFlags(&evG2, cudaEventDisableTiming);
        cudaEventCreateWithFlags(&evG3, cudaEventDisableTiming);
        cudaEventCreateWithFlags(&evA1, cudaEventDisableTiming);
        cudaEventCreateWithFlags(&evA2, cudaEventDisableTiming);
        cudaFuncSetAttribute(k_gemm2<128>, cudaFuncAttributeMaxDynamicSharedMemorySize,
                             64 * 128 * 8);
        cudaFuncSetAttribute(k_gemm2<16>, cudaFuncAttributeMaxDynamicSharedMemorySize,
                             64 * 16 * 8);
    }

    void *ph, *px1, *px2;
    cudaGetSymbolAddress(&ph, g_h);
    cudaGetSymbolAddress(&px1, g_x1);
    cudaGetSymbolAddress(&px2, g_x2);
    float* h = (float*)ph;
    float* x1 = (float*)px1;
    float* x2 = (float*)px2;

    const int TB = 256;
    const int nbN = (NN + TB - 1) / TB;         // 196
    const int nbNw = (NN * 32 + TB - 1) / TB;   // 6250 (warp per node)
    const int nbNh = (NN * 16 + TB - 1) / TB;   // 3125 (16 threads per node)

    // fork side stream
    cudaEventRecord(evF, 0);
    cudaStreamWaitEvent(s2, evF, 0);

    // s2: GEMM1 (only depends on x0, W1)
    k_gemm2<128><<<(NN + 31) / 32, 256, 64 * 128 * 8, s2>>>(x0, W1, h);
    cudaEventRecord(evG1, s2);

    // main: CSR build + norms + attention chain for layer 1
    k_fill_invn<<<6250 + nbNw, TB>>>(src, dst, x0);
    k_sim128<<<nbNw, TB>>>(x0);
    k_degC<<<nbNh, TB>>>();
    cudaStreamWaitEvent(0, evG1, 0);
    k_agg128<<<nbNw, TB>>>(h, b1, x1);    // + relu + invn(x1) + re-zero
    cudaEventRecord(evA1, 0);

    // s2: GEMM2 after agg128 produced x1 (g_h free again after agg128)
    cudaStreamWaitEvent(s2, evA1, 0);
    k_gemm2<16><<<(NN + 63) / 64, 256, 64 * 16 * 8, s2>>>(x1, W2, h);
    cudaEventRecord(evG2, s2);

    // main: layer-2 attention chain (overlaps gemm2)
    k_sim128<<<nbNw, TB>>>(x1);
    k_degC<<<nbNh, TB>>>();
    cudaStreamWaitEvent(0, evG2, 0);
    k_agg16<<<nbNw, TB>>>(h, b2, x2);     // + relu + invn(x2) + re-zero
    cudaEventRecord(evA2, 0);

    // s2: GEMM3 after agg16 produced x2
    cudaStreamWaitEvent(s2, evA2, 0);
    k_gemm_k16n40<<<nbN, TB, 0, s2>>>(x2, W3, h);
    cudaEventRecord(evG3, s2);

    // main: layer-3 attention chain (overlaps gemm3)
    k_sim16<<<nbNw, TB>>>(x2);
    k_degC<<<nbNh, TB>>>();
    cudaStreamWaitEvent(0, evG3, 0);
    k_agg40lsm<<<nbNw, TB>>>(h, b3, out);  // + re-zero rowsum/degf/cnt
}

// round 17
// speedup vs baseline: 1.1180x; 1.0022x over previous
#include <cuda_runtime.h>
#include <math.h>

#define NN 50000
#define NE 1600000
#define CAP 128

typedef unsigned long long u64;
#define FULL 0xffffffffu

// ---------------- device scratch (no allocations allowed) ----------------
__device__ int   g_cnt[NN];          // zero at load; re-zeroed by agg40lsm
__device__ int   g_bsrc[NN * CAP];   // bucketed src lists by dst
__device__ float g_bw[NN * CAP];     // edge weight per bucket slot
__device__ float g_invn[NN];
__device__ float g_rowsum[NN];
__device__ float g_degf[NN];
__device__ float g_dinv[NN];
__device__ float g_cnode[NN];
__device__ float g_rd[NN];           // rinv * dinv (src-side combined)
__device__ float g_h[NN * 128];
__device__ float g_x1[NN * 128];
__device__ float g_x2[NN * 16];

// ---------------- helpers ----------------
__device__ __forceinline__ float warp_sum(float v) {
    #pragma unroll
    for (int o = 16; o; o >>= 1) v += __shfl_xor_sync(FULL, v, o);
    return v;
}
__device__ __forceinline__ float warp_max(float v) {
    #pragma unroll
    for (int o = 16; o; o >>= 1) v = fmaxf(v, __shfl_xor_sync(FULL, v, o));
    return v;
}
__device__ __forceinline__ void fma2(u64& d, u64 a, u64 b) {
    asm("fma.rn.f32x2 %0, %1, %2, %0;" : "+l"(d) : "l"(a), "l"(b));
}
__device__ __forceinline__ u64 pack2(float lo, float hi) {
    u64 v;
    asm("mov.b64 %0, {%1, %2};" : "=l"(v) : "f"(lo), "f"(hi));
    return v;
}
__device__ __forceinline__ float2 unpack2(u64 v) {
    float2 r;
    asm("mov.b64 {%0, %1}, %2;" : "=f"(r.x), "=f"(r.y) : "l"(v));
    return r;
}
__device__ __forceinline__ float dot44(float4 a, float4 b) {
    return a.x * b.x + a.y * b.y + a.z * b.z + a.w * b.w;
}

// ---- fused: bucket fill (blocks 0..6249) + invn128 (2 nodes/warp) --------
__global__ void k_fill_invn(const int* __restrict__ src, const int* __restrict__ dst,
                            const float* __restrict__ x) {
    if (blockIdx.x < 6250) {
        int e = blockIdx.x * 256 + threadIdx.x;
        if (e < NE) {
            int d = dst[e];
            int p = atomicAdd(&g_cnt[d], 1);
            if (p < CAP) g_bsrc[d * CAP + p] = src[e];
        }
    } else {
        int idx = (blockIdx.x - 6250) * 256 + threadIdx.x;
        int w = idx >> 4;              // 16 threads per node
        int hl = threadIdx.x & 15;
        if (w >= NN) return;
        const float4* row = (const float4*)(x + (size_t)w * 128);
        float4 v0 = row[hl];
        float4 v1 = row[hl + 16];
        float s = dot44(v0, v0) + dot44(v1, v1);
        #pragma unroll
        for (int o = 8; o; o >>= 1) s += __shfl_xor_sync(FULL, s, o);
        if (hl == 0) g_invn[w] = (s > 0.f) ? rsqrtf(s) : 0.f;
    }
}

// -- sim: 8 lanes/edge, 4 edges/iter, software-pipelined (R13 exact) -------
__global__ void k_sim128(const float* __restrict__ x) {
    int node = (blockIdx.x * blockDim.x + threadIdx.x) >> 5;
    int lane = threadIdx.x & 31;
    if (node >= NN) return;
    int g = (lane >> 3) & 3;   // edge group 0..3
    int j = lane & 7;          // float4 slot within group
    const float4* xr = (const float4*)x;
    const float4* brow = xr + (size_t)node * 32 + j;
    float4 b0 = brow[0], b1 = brow[8], b2 = brow[16], b3 = brow[24];
    float invd = g_invn[node];
    int cnt = min(g_cnt[node], CAP);
    if (cnt <= 0) return;
    const int* bs = g_bsrc + node * CAP;
    float* bw = g_bw + node * CAP;
    // prologue: load quad 0
    int s_cur = bs[(g < cnt) ? g : 0];
    const float4* ar = xr + (size_t)s_cur * 32 + j;
    float4 a0 = ar[0], a1 = ar[8], a2 = ar[16], a3 = ar[24];
    for (int p = 0; p < cnt; p += 4) {
        // prefetch next quad (index 0 is always valid; rows clamp to bs[0])
        int inx = p + 4 + g;
        int s_nxt = bs[(inx < cnt) ? inx : 0];
        const float4* an = xr + (size_t)s_nxt * 32 + j;
        float4 n0 = an[0], n1 = an[8], n2 = an[16], n3 = an[24];
        // reduce current quad
        float t = dot44(a0, b0) + dot44(a1, b1) + dot44(a2, b2) + dot44(a3, b3);
        t += __shfl_xor_sync(FULL, t, 4);
        t += __shfl_xor_sync(FULL, t, 2);
        t += __shfl_xor_sync(FULL, t, 1);
        int icur = p + g;
        if (j == 0 && icur < cnt) {
            float sim = t * g_invn[s_cur] * invd;
            float wv = (sim >= 0.5f && s_cur != node) ? sim : 0.f;
            bw[icur] = wv;
            if (wv != 0.f) {
                atomicAdd(&g_rowsum[s_cur], wv);
                atomicAdd(&g_degf[s_cur], 1.f);
            }
        }
        a0 = n0; a1 = n1; a2 = n2; a3 = n3;
        s_cur = s_nxt;
    }
}

// 16-dim sim: warp per node, lane per bucket slot
__global__ void k_sim16(const float* __restrict__ x) {
    int node = (blockIdx.x * blockDim.x + threadIdx.x) >> 5;
    int lane = threadIdx.x & 31;
    if (node >= NN) return;
    const float4* pb = (const float4*)(x + (size_t)node * 16);
    float4 b0 = pb[0], b1 = pb[1], b2 = pb[2], b3 = pb[3];
    float invd = g_invn[node];
    int cnt = min(g_cnt[node], CAP);
    const int* bs = g_bsrc + node * CAP;
    float* bw = g_bw + node * CAP;
    for (int p = lane; p < cnt; p += 32) {
        int s = bs[p];
        const float4* pa = (const float4*)(x + (size_t)s * 16);
        float t = dot44(pa[0], b0) + dot44(pa[1], b1) + dot44(pa[2], b2) + dot44(pa[3], b3);
        float sim = t * g_invn[s] * invd;
        float wv = (sim >= 0.5f && s != node) ? sim : 0.f;
        bw[p] = wv;
        if (wv != 0.f) {
            atomicAdd(&g_rowsum[s], wv);
            atomicAdd(&g_degf[s], 1.f);
        }
    }
}

// ------- gcn degree + dinv/cnode/rd: 4 nodes per warp (8 lanes each) ------
__global__ void k_degC() {
    int idx = blockIdx.x * blockDim.x + threadIdx.x;
    int node = idx >> 3;               // 8 threads per node
    int hl = threadIdx.x & 7;          // lane within octet
    if (node >= NN) return;
    int cnt = min(g_cnt[node], CAP);
    const int* bs = g_bsrc + node * CAP;
    const float* bw = g_bw + node * CAP;
    float acc = 0.f;
    for (int p = hl; p < cnt; p += 8) {
        float wv = bw[p];
        if (wv != 0.f) acc += wv * (1.f / g_rowsum[bs[p]]);  // rowsum>=wv>0
    }
    #pragma unroll
    for (int o = 4; o; o >>= 1) acc += __shfl_xor_sync(FULL, acc, o);
    if (hl == 0) {
        float sw = 1.f / (g_degf[node] + 1.f);
        float dv = rsqrtf(acc + sw);   // sw > 0 always
        g_dinv[node] = dv;
        g_cnode[node] = sw * dv * dv;
        float rs = g_rowsum[node];
        float rinv = (rs == 0.f) ? 1.f : 1.f / rs;
        g_rd[node] = rinv * dv;
    }
}

// ---------------- GEMM (K=128) with packed f32x2 FMA ----------------------
template <int N>
__global__ void __launch_bounds__(256) k_gemm2(const float* __restrict__ A,
                                               const float* __restrict__ W,
                                               float* __restrict__ C) {
    constexpr int CG = N / 4;
    constexpr int BR = (N == 128) ? 32 : 64;
    constexpr int RT = BR * CG / 256;
    extern __shared__ u64 Ws2[];
    for (int i = threadIdx.x; i < 64 * N; i += 256) {
        int kp = i / N, c = i % N;
        Ws2[i] = pack2(W[(2 * kp) * N + c], W[(2 * kp + 1) * N + c]);
    }
    __syncthreads();
    int cg = threadIdx.x % CG;
    int r0 = blockIdx.x * BR + (threadIdx.x / CG) * RT;
    const float4* A4 = (const float4*)A;
    u64 acc[RT][4];
    int rr[RT];
    #pragma unroll
    for (int i = 0; i < RT; i++) {
        acc[i][0] = acc[i][1] = acc[i][2] = acc[i][3] = 0ull;
        rr[i] = min(r0 + i, NN - 1);
    }
    for (int kq = 0; kq < 32; kq++) {
        const u64* w0 = Ws2 + (2 * kq) * N + cg * 4;
        const u64* w1 = w0 + N;
        u64 wa0 = w0[0], wa1 = w0[1], wa2 = w0[2], wa3 = w0[3];
        u64 wb0 = w1[0], wb1 = w1[1], wb2 = w1[2], wb3 = w1[3];
        #pragma unroll
        for (int i = 0; i < RT; i++) {
            float4 a = A4[(size_t)rr[i] * 32 + kq];
            u64 a01 = pack2(a.x, a.y);
            u64 a23 = pack2(a.z, a.w);
            fma2(acc[i][0], a01, wa0); fma2(acc[i][0], a23, wb0);
            fma2(acc[i][1], a01, wa1); fma2(acc[i][1], a23, wb1);
            fma2(acc[i][2], a01, wa2); fma2(acc[i][2], a23, wb2);
            fma2(acc[i][3], a01, wa3); fma2(acc[i][3], a23, wb3);
        }
    }
    #pragma unroll
    for (int i = 0; i < RT; i++) {
        int gr = r0 + i;
        if (gr < NN) {
            float2 c0 = unpack2(acc[i][0]), c1 = unpack2(acc[i][1]);
            float2 c2 = unpack2(acc[i][2]), c3 = unpack2(acc[i][3]);
            *(float4*)(C + (size_t)gr * N + cg * 4) =
                make_float4(c0.x + c0.y, c1.x + c1.y, c2.x + c2.y, c3.x + c3.y);
        }
    }
}

__global__ void k_gemm_k16n40(const float* __restrict__ A, const float* __restrict__ W,
                              float* __restrict__ C) {
    __shared__ float Ws[16 * 40];
    for (int i = threadIdx.x; i < 640; i += blockDim.x) Ws[i] = W[i];
    __syncthreads();
    int r = blockIdx.x * blockDim.x + threadIdx.x;
    if (r >= NN) return;
    float a[16];
    const float4* p = (const float4*)(A + (size_t)r * 16);
    #pragma unroll
    for (int j = 0; j < 4; j++) {
        float4 v = p[j];
        a[j * 4 + 0] = v.x; a[j * 4 + 1] = v.y; a[j * 4 + 2] = v.z; a[j * 4 + 3] = v.w;
    }
    float acc[40];
    #pragma unroll
    for (int c = 0; c < 40; c++) acc[c] = 0.f;
    #pragma unroll
    for (int k = 0; k < 16; k++) {
        float av = a[k];
        #pragma unroll
        for (int c = 0; c < 40; c++) acc[c] += av * Ws[k * 40 + c];
    }
    float* out = C + (size_t)r * 40;
    #pragma unroll
    for (int c = 0; c < 40; c += 4)
        *(float4*)(out + c) = make_float4(acc[c], acc[c + 1], acc[c + 2], acc[c + 3]);
}

// ---------------- aggregation (ballot-compacted edge loop, R13) -----------
__global__ void k_agg128(const float* __restrict__ h, const float* __restrict__ b,
                         float* __restrict__ out) {
    int node = (blockIdx.x * blockDim.x + threadIdx.x) >> 5;
    int lane = threadIdx.x & 31;
    if (node >= NN) return;
    float dv = g_dinv[node];
    float c0 = g_cnode[node];
    const float4* hr = (const float4*)h;
    int cnt = min(g_cnt[node], CAP);
    const int* bs = g_bsrc + node * CAP;
    const float* bw = g_bw + node * CAP;
    float4 hv = hr[(size_t)node * 32 + lane];
    float4 bv = ((const float4*)b)[lane];
    float4 acc = make_float4(c0 * hv.x + bv.x, c0 * hv.y + bv.y,
                             c0 * hv.z + bv.z, c0 * hv.w + bv.w);
    for (int base = 0; base < cnt; base += 32) {
        int i = base + lane;
        float wv = (i < cnt) ? bw[i] : 0.f;
        int sl = (i < cnt) ? bs[i] : 0;
        float cl = (wv != 0.f) ? wv * g_rd[sl] * dv : 0.f;
        unsigned m = __ballot_sync(FULL, wv != 0.f);
        while (m) {
            int bit = __ffs(m) - 1;
            m &= m - 1;
            float c = __shfl_sync(FULL, cl, bit);
            int s = __shfl_sync(FULL, sl, bit);
            float4 xv = hr[(size_t)s * 32 + lane];
            acc.x += c * xv.x; acc.y += c * xv.y; acc.z += c * xv.z; acc.w += c * xv.w;
        }
    }
    acc.x = fmaxf(acc.x, 0.f); acc.y = fmaxf(acc.y, 0.f);
    acc.z = fmaxf(acc.z, 0.f); acc.w = fmaxf(acc.w, 0.f);
    ((float4*)(out + (size_t)node * 128))[lane] = acc;
    float s2 = warp_sum(dot44(acc, acc));
    if (lane == 0) {
        g_invn[node] = (s2 > 0.f) ? rsqrtf(s2) : 0.f;
        g_rowsum[node] = 0.f;
        g_degf[node] = 0.f;
    }
}

__global__ void k_agg16(const float* __restrict__ h, const float* __restrict__ b,
                        float* __restrict__ out) {
    int node = (blockIdx.x * blockDim.x + threadIdx.x) >> 5;
    int lane = threadIdx.x & 31;
    if (node >= NN) return;
    int j = lane & 15;
    float dv = g_dinv[node];
    float c0 = g_cnode[node];
    int cnt = min(g_cnt[node], CAP);
    const int* bs = g_bsrc + node * CAP;
    const float* bw = g_bw + node * CAP;
    float acc = 0.f;
    for (int base = 0; base < cnt; base += 32) {
        int i = base + lane;
        float wv = (i < cnt) ? bw[i] : 0.f;
        int sl = (i < cnt) ? bs[i] : 0;
        float cl = (wv != 0.f) ? wv * g_rd[sl] * dv : 0.f;
        unsigned m = __ballot_sync(FULL, wv != 0.f);
        while (m) {
            int bit = __ffs(m) - 1;
            m &= m - 1;
            float c = __shfl_sync(FULL, cl, bit);
            int s = __shfl_sync(FULL, sl, bit);
            acc += c * h[(size_t)s * 16 + j];
        }
    }
    float r = fmaxf(acc + c0 * h[(size_t)node * 16 + j] + b[j], 0.f);
    if (lane < 16) out[(size_t)node * 16 + j] = r;
    float s2 = warp_sum((lane < 16) ? r * r : 0.f);
    if (lane == 0) {
        g_invn[node] = (s2 > 0.f) ? rsqrtf(s2) : 0.f;
        g_rowsum[node] = 0.f;
        g_degf[node] = 0.f;
    }
}

__global__ void k_agg40lsm(const float* __restrict__ h, const float* __restrict__ b,
                           float* __restrict__ out) {
    int node = (blockIdx.x * blockDim.x + threadIdx.x) >> 5;
    int lane = threadIdx.x & 31;
    if (node >= NN) return;
    float dv = g_dinv[node];
    float c0 = g_cnode[node];
    const float* hn = h + (size_t)node * 40;
    float a0 = c0 * hn[lane] + b[lane];
    float a1 = (lane < 8) ? c0 * hn[32 + lane] + b[32 + lane] : 0.f;
    int cnt = min(g_cnt[node], CAP);
    const int* bs = g_bsrc + node * CAP;
    const float* bw = g_bw + node * CAP;
    for (int base = 0; base < cnt; base += 32) {
        int i = base + lane;
        float wv = (i < cnt) ? bw[i] : 0.f;
        int sl = (i < cnt) ? bs[i] : 0;
        float cl = (wv != 0.f) ? wv * g_rd[sl] * dv : 0.f;
        unsigned m = __ballot_sync(FULL, wv != 0.f);
        while (m) {
            int bit = __ffs(m) - 1;
            m &= m - 1;
            float c = __shfl_sync(FULL, cl, bit);
            int s = __shfl_sync(FULL, sl, bit);
            const float* hs = h + (size_t)s * 40;
            a0 += c * hs[lane];
            if (lane < 8) a1 += c * hs[32 + lane];
        }
    }
    float m = warp_max((lane < 8) ? fmaxf(a0, a1) : a0);
    float se = warp_sum(expf(a0 - m) + ((lane < 8) ? expf(a1 - m) : 0.f));
    float l = logf(se) + m;
    float* on = out + (size_t)node * 40;
    on[lane] = a0 - l;
    if (lane < 8) on[32 + lane] = a1 - l;
    if (lane == 0) {            // leave all per-call accumulators zeroed
        g_rowsum[node] = 0.f;
        g_degf[node] = 0.f;
        g_cnt[node] = 0;
    }
}

// ---------------- launch ----------------
extern "C" void kernel_launch(void* const* d_in, const int* in_sizes, int n_in,
                              void* d_out, int out_size) {
    const float* x0 = (const float*)d_in[0];
    const int* ei = (const int*)d_in[1];
    const float* W1 = (const float*)d_in[2];
    const float* b1 = (const float*)d_in[3];
    const float* W2 = (const float*)d_in[4];
    const float* b2 = (const float*)d_in[5];
    const float* W3 = (const float*)d_in[6];
    const float* b3 = (const float*)d_in[7];
    const int* src = ei;
    const int* dst = ei + NE;
    float* out = (float*)d_out;

    // one-time host-side resources (no device memory involved)
    static cudaStream_t s2 = nullptr;
    static cudaEvent_t evF, evG1, evG2, evG3, evA1, evA2;
    if (!s2) {
        cudaStreamCreateWithFlags(&s2, cudaStreamNonBlocking);
        cudaEventCreateWithFlags(&evF, cudaEventDisableTiming);
        cudaEventCreateWithFlags(&evG1, cudaEventDisableTiming);
        cudaEventCreateWithFlags(&evG2, cudaEventDisableTiming);
        cudaEventCreateWithFlags(&evG3, cudaEventDisableTiming);
        cudaEventCreateWithFlags(&evA1, cudaEventDisableTiming);
        cudaEventCreateWithFlags(&evA2, cudaEventDisableTiming);
        cudaFuncSetAttribute(k_gemm2<128>, cudaFuncAttributeMaxDynamicSharedMemorySize,
                             64 * 128 * 8);
        cudaFuncSetAttribute(k_gemm2<16>, cudaFuncAttributeMaxDynamicSharedMemorySize,
                             64 * 16 * 8);
    }

    void *ph, *px1, *px2;
    cudaGetSymbolAddress(&ph, g_h);
    cudaGetSymbolAddress(&px1, g_x1);
    cudaGetSymbolAddress(&px2, g_x2);
    float* h = (float*)ph;
    float* x1 = (float*)px1;
    float* x2 = (float*)px2;

    const int TB = 256;
    const int nbN = (NN + TB - 1) / TB;         // 196
    const int nbNw = (NN * 32 + TB - 1) / TB;   // 6250 (warp per node)
    const int nbNh = (NN * 16 + TB - 1) / TB;   // 3125 (16 thr/node)
    const int nbNq = (NN * 8 + TB - 1) / TB;    // 1563 (8 thr/node)

    // fork side stream
    cudaEventRecord(evF, 0);
    cudaStreamWaitEvent(s2, evF, 0);

    // s2: GEMM1 (only depends on x0, W1)
    k_gemm2<128><<<(NN + 31) / 32, 256, 64 * 128 * 8, s2>>>(x0, W1, h);
    cudaEventRecord(evG1, s2);

    // main: CSR build + norms + attention chain for layer 1
    k_fill_invn<<<6250 + nbNh, TB>>>(src, dst, x0);
    k_sim128<<<nbNw, TB>>>(x0);
    k_degC<<<nbNq, TB>>>();
    cudaStreamWaitEvent(0, evG1, 0);
    k_agg128<<<nbNw, TB>>>(h, b1, x1);    // + relu + invn(x1) + re-zero
    cudaEventRecord(evA1, 0);

    // s2: GEMM2 after agg128 produced x1 (g_h free again after agg128)
    cudaStreamWaitEvent(s2, evA1, 0);
    k_gemm2<16><<<(NN + 63) / 64, 256, 64 * 16 * 8, s2>>>(x1, W2, h);
    cudaEventRecord(evG2, s2);

    // main: layer-2 attention chain (overlaps gemm2)
    k_sim128<<<nbNw, TB>>>(x1);
    k_degC<<<nbNq, TB>>>();
    cudaStreamWaitEvent(0, evG2, 0);
    k_agg16<<<nbNw, TB>>>(h, b2, x2);     // + relu + invn(x2) + re-zero
    cudaEventRecord(evA2, 0);

    // s2: GEMM3 after agg16 produced x2
    cudaStreamWaitEvent(s2, evA2, 0);
    k_gemm_k16n40<<<nbN, TB, 0, s2>>>(x2, W3, h);
    cudaEventRecord(evG3, s2);

    // main: layer-3 attention chain (overlaps gemm3)
    k_sim16<<<nbNw, TB>>>(x2);
    k_degC<<<nbNq, TB>>>();
    cudaStreamWaitEvent(0, evG3, 0);
    k_agg40lsm<<<nbNw, TB>>>(h, b3, out);  // + re-zero rowsum/degf/cnt
}